// round 15
// baseline (speedup 1.0000x reference)
#include <cuda_runtime.h>
#include <cuda_bf16.h>
#include <mma.h>
#include <cstdint>
#include <cstddef>
using namespace nvcuda;

// ---------------- problem constants ----------------
#define LSEQ   64
#define BATCH  256
#define NIO    4
#define NB     1024      // BATCH*NIO
#define IO_EMB 128
#define XDIM   256       // 2*IO_EMB
#define HID    512       // IO_HID
#define GATE   2048      // 4*HID
#define KCAT   768       // XDIM + HID
#define EH     1024      // ENC_HID
#define VG     4096      // 4*EH
#define TDEC   32
#define NPROD  64
#define TB     (TDEC * BATCH)   // 8192

// ---------------- device scratch (static, no allocs) ----------------
__device__ __nv_bfloat16 g_x[(size_t)LSEQ * NB * XDIM];
__device__ __nv_bfloat16 g_h2[2][(size_t)2 * NB * HID];      // encoder h parity buffers
__device__ __nv_bfloat16 g_Wcat[2 * KCAT * GATE];            // interleaved: col = 4*u + gate
__device__ float g_c_enc[2 * NB * HID];
__device__ __nv_bfloat16 g_hs_f[(size_t)LSEQ * NB * HID];
__device__ __nv_bfloat16 g_hs_b[(size_t)LSEQ * NB * HID];
__device__ float g_c_dec[BATCH * EH];
__device__ __nv_bfloat16 g_hdec_bf[2 * BATCH * EH];          // parity double buffer
__device__ __nv_bfloat16 g_feat[(size_t)TB * 2048];          // [t*256+b][ h(1024) | ctxp(1024) ]
__device__ float g_q_all[(size_t)TB * EH];
__device__ __nv_bfloat16 g_ctx_bf[(size_t)TDEC * NB * EH];   // bf16 ctx
__device__ float g_vXWi[TDEC * VG];                          // interleaved gates (fp32, by helpers)
__device__ __nv_bfloat16 g_Wattn_bf[EH * EH];
__device__ __nv_bfloat16 g_vWh_bf[EH * VG];                  // interleaved
__device__ __nv_bfloat16 g_Wcls_bf[2048 * NPROD];
__device__ float g_nll[TB];

// grid-barrier state (reset every call in k_init / k_pool)
__device__ unsigned g_barA_cnt, g_barA_gen;
__device__ unsigned g_barB_cnt, g_barB_gen;

// fast activations
__device__ __forceinline__ float ftanh(float x) {
    float y;
    asm("tanh.approx.f32 %0, %1;" : "=f"(y) : "f"(x));
    return y;
}
__device__ __forceinline__ float fsig(float x) { return fmaf(ftanh(x * 0.5f), 0.5f, 0.5f); }

// split grid barrier
__device__ __forceinline__ void bar_arrive(unsigned* cnt, unsigned* gen, unsigned nblk,
                                           unsigned my) {
    __syncthreads();
    if (threadIdx.x == 0) {
        __threadfence();
        unsigned old = atomicAdd(cnt, 1u);
        if (old == nblk - 1) {
            *cnt = 0u;
            __threadfence();
            atomicExch(gen, my + 1u);
        }
    }
}
__device__ __forceinline__ void bar_wait(unsigned* gen, unsigned my) {
    if (threadIdx.x == 0) {
        while (atomicAdd(gen, 0u) <= my) { }
        __threadfence();
    }
    __syncthreads();
}

// ---------------- cp.async helpers ----------------
__device__ __forceinline__ void cp16(void* dst, const void* src, bool valid) {
    unsigned int d = (unsigned int)__cvta_generic_to_shared(dst);
    int sz = valid ? 16 : 0;
    asm volatile("cp.async.cg.shared.global [%0], [%1], 16, %2;" :: "r"(d), "l"(src), "r"(sz));
}
__device__ __forceinline__ void cp_commit() { asm volatile("cp.async.commit_group;"); }
__device__ __forceinline__ void cp_wait1()  { asm volatile("cp.async.wait_group 1;"); }
__device__ __forceinline__ void cp_wait0()  { asm volatile("cp.async.wait_group 0;"); }

#define BM 128
#define BN 128
#define BK 32

// ---------------- 128x128 bf16 tensor-core GEMM ----------------
__global__ void __launch_bounds__(256) gemm_bf16(
    const __nv_bfloat16* __restrict__ A, const __nv_bfloat16* __restrict__ B,
    float* __restrict__ C, int M, int N, int K, int lda, int ldb, int ldc)
{
    __shared__ __nv_bfloat16 As[2][BM][40];
    __shared__ __nv_bfloat16 Bs[2][BK][136];

    int tid  = threadIdx.x;
    int warp = tid >> 5;
    int wr = warp >> 1, wc = warp & 1;
    int brow = blockIdx.y * BM, bcol = blockIdx.x * BN;
    int m0 = wr * 32, n0 = wc * 64;

    wmma::fragment<wmma::accumulator, 16, 16, 16, float> acc[2][4];
#pragma unroll
    for (int i = 0; i < 2; i++)
#pragma unroll
        for (int j = 0; j < 4; j++)
            wmma::fill_fragment(acc[i][j], 0.f);

    int nk = K / BK;

    auto load_tile = [&](int buf, int k0) {
#pragma unroll
        for (int i = 0; i < 2; i++) {
            int cid = tid + i * 256;
            int row = cid >> 2;
            int col = (cid & 3) * 8;
            const __nv_bfloat16* src = A + (size_t)(brow + row) * lda + k0 + col;
            bool v = (brow + row) < M;
            cp16(&As[buf][row][col], v ? (const void*)src : (const void*)A, v);
        }
#pragma unroll
        for (int i = 0; i < 2; i++) {
            int cid = tid + i * 256;
            int row = cid >> 4;
            int col = (cid & 15) * 8;
            cp16(&Bs[buf][row][col], B + (size_t)(k0 + row) * ldb + bcol + col, true);
        }
    };

    load_tile(0, 0);
    cp_commit();

    int buf = 0;
    for (int kt = 0; kt < nk; kt++) {
        if (kt + 1 < nk) { load_tile(buf ^ 1, (kt + 1) * BK); cp_commit(); cp_wait1(); }
        else             { cp_wait0(); }
        __syncthreads();
#pragma unroll
        for (int kk = 0; kk < BK; kk += 16) {
            wmma::fragment<wmma::matrix_a, 16, 16, 16, __nv_bfloat16, wmma::row_major> af[2];
            wmma::fragment<wmma::matrix_b, 16, 16, 16, __nv_bfloat16, wmma::row_major> bfr[4];
#pragma unroll
            for (int i = 0; i < 2; i++)
                wmma::load_matrix_sync(af[i], &As[buf][m0 + i * 16][kk], 40);
#pragma unroll
            for (int j = 0; j < 4; j++)
                wmma::load_matrix_sync(bfr[j], &Bs[buf][kk][n0 + j * 16], 136);
#pragma unroll
            for (int i = 0; i < 2; i++)
#pragma unroll
                for (int j = 0; j < 4; j++)
                    wmma::mma_sync(acc[i][j], af[i], bfr[j], acc[i][j]);
        }
        __syncthreads();
        buf ^= 1;
    }

#pragma unroll
    for (int i = 0; i < 2; i++) {
        int gm = brow + m0 + i * 16;
        if (gm >= M) continue;
#pragma unroll
        for (int j = 0; j < 4; j++)
            wmma::store_matrix_sync(&C[(size_t)gm * ldc + bcol + n0 + j * 16],
                                    acc[i][j], ldc, wmma::mem_row_major);
    }
}

// ---------------- fused classifier GEMM + NLL ----------------
__global__ void __launch_bounds__(128) gemm_cls(
    const float* __restrict__ b_comp, const int* __restrict__ actions)
{
    __shared__ __align__(16) char smu[19456];
    __nv_bfloat16 (*As)[64][40] = reinterpret_cast<__nv_bfloat16(*)[64][40]>(smu);
    __nv_bfloat16 (*Bs)[32][72] = reinterpret_cast<__nv_bfloat16(*)[32][72]>(smu + 10240);
    float* Cs = reinterpret_cast<float*>(smu);   // [64][68] (union, post-loop)

    int tid = threadIdx.x, warp = tid >> 5;
    int m0 = (warp & 1) * 32, n0 = (warp >> 1) * 32;
    int brow = blockIdx.y * 64;
    const __nv_bfloat16* A = g_feat + (size_t)brow * 2048;

    wmma::fragment<wmma::accumulator, 16, 16, 16, float> acc[2][2];
#pragma unroll
    for (int i = 0; i < 2; i++)
#pragma unroll
        for (int j = 0; j < 2; j++)
            wmma::fill_fragment(acc[i][j], 0.f);

    auto load_tile = [&](int buf, int k0) {
#pragma unroll
        for (int i = 0; i < 2; i++) {
            int cid = tid + i * 128;
            int row = cid >> 2, col = (cid & 3) * 8;
            cp16(&As[buf][row][col], A + (size_t)row * 2048 + k0 + col, true);
        }
#pragma unroll
        for (int i = 0; i < 2; i++) {
            int cid = tid + i * 128;
            int row = cid >> 3, col = (cid & 7) * 8;
            cp16(&Bs[buf][row][col], g_Wcls_bf + (size_t)(k0 + row) * NPROD + col, true);
        }
    };

    load_tile(0, 0);
    cp_commit();
    int buf = 0;
    for (int kt = 0; kt < 64; kt++) {
        if (kt + 1 < 64) { load_tile(buf ^ 1, (kt + 1) * 32); cp_commit(); cp_wait1(); }
        else             { cp_wait0(); }
        __syncthreads();
#pragma unroll
        for (int kk = 0; kk < 32; kk += 16) {
            wmma::fragment<wmma::matrix_a, 16, 16, 16, __nv_bfloat16, wmma::row_major> af[2];
            wmma::fragment<wmma::matrix_b, 16, 16, 16, __nv_bfloat16, wmma::row_major> bfr[2];
#pragma unroll
            for (int i = 0; i < 2; i++)
                wmma::load_matrix_sync(af[i], &As[buf][m0 + i * 16][kk], 40);
#pragma unroll
            for (int j = 0; j < 2; j++)
                wmma::load_matrix_sync(bfr[j], &Bs[buf][kk][n0 + j * 16], 72);
#pragma unroll
            for (int i = 0; i < 2; i++)
#pragma unroll
                for (int j = 0; j < 2; j++)
                    wmma::mma_sync(acc[i][j], af[i], bfr[j], acc[i][j]);
        }
        __syncthreads();
        buf ^= 1;
    }

#pragma unroll
    for (int i = 0; i < 2; i++)
#pragma unroll
        for (int j = 0; j < 2; j++)
            wmma::store_matrix_sync(&Cs[(m0 + i * 16) * 68 + n0 + j * 16], acc[i][j], 68,
                                    wmma::mem_row_major);
    __syncthreads();

    if (tid < 64) {
        int row = tid;
        float mx = -1e30f;
        for (int j = 0; j < NPROD; j++)
            mx = fmaxf(mx, Cs[row * 68 + j] + b_comp[j]);
        float sum = 0.f;
        for (int j = 0; j < NPROD; j++)
            sum += __expf(Cs[row * 68 + j] + b_comp[j] - mx);
        int tb = brow + row;
        int t = tb >> 8, b = tb & 255;
        int a = actions[b * TDEC + t];
        g_nll[tb] = mx + __logf(sum) - (Cs[row * 68 + a] + b_comp[a]);
    }
}

// ---------------- persistent encoder (3-stage pipe) + helper blocks ----------------
// 148 blocks: 0-127 workers; 128-147 helpers (conversions + vXWi fp32), exit early.
// smem: As[3][128][72] @0 (55296) | Bs[3][64][264] @55296 (101376); Cs f32 [128][260] union.
#define ENC_DYN 156672
__global__ void __launch_bounds__(512) enc_persist(
    const float* __restrict__ b_f, const float* __restrict__ b_b,
    const float* __restrict__ W_attn, const float* __restrict__ v_Wi,
    const float* __restrict__ v_Wh, const float* __restrict__ field,
    const float* __restrict__ W_comp)
{
    extern __shared__ __align__(16) char dyn[];
    int tid = threadIdx.x;
    int bid = blockIdx.x;

    if (bid >= 128) {   // helpers: conversions + vXWi (hidden under encoder)
        const int NH = 20 * 512;
        int hid = (bid - 128) * 512 + tid;
        for (int idx = hid; idx < EH * VG; idx += NH) {
            int k = idx >> 12, n = idx & 4095;
            int u = n >> 2, g = n & 3;
            g_vWh_bf[idx] = __float2bfloat16(v_Wh[k * VG + g * 1024 + u]);
        }
        for (int idx = hid; idx < EH * EH; idx += NH)
            g_Wattn_bf[idx] = __float2bfloat16(W_attn[idx]);
        for (int idx = hid; idx < 2048 * NPROD; idx += NH)
            g_Wcls_bf[idx] = __float2bfloat16(W_comp[idx]);
        // vXWi = field @ v_Wi (interleaved), fp32
        for (int idx = hid; idx < TDEC * VG; idx += NH) {
            int t = idx >> 12;
            int n = idx & 4095;
            int u = n >> 2, g = n & 3;
            int col = g * 1024 + u;
            float s = 0.f;
            for (int k = 0; k < EH; k++)
                s = fmaf(field[t * EH + k], v_Wi[(size_t)k * VG + col], s);
            g_vXWi[idx] = s;
        }
        return;
    }

    __nv_bfloat16 (*As)[128][72] = reinterpret_cast<__nv_bfloat16(*)[128][72]>(dyn);
    __nv_bfloat16 (*Bs)[64][264] = reinterpret_cast<__nv_bfloat16(*)[64][264]>(dyn + 55296);
    float* Cs = reinterpret_cast<float*>(dyn);           // [128][260] (union)

    int warp = tid >> 5;
    int wr = warp >> 2, wc = warp & 3;
    int dir = bid >> 6;
    int rt = (bid >> 3) & 7, ct = bid & 7;
    int brow = rt * 128, bcol = ct * 256;
    int m0 = wr * 32, n0 = wc * 64;

    const __nv_bfloat16* Wcat = g_Wcat + (size_t)dir * KCAT * GATE;
    const float* bias = dir ? b_b : b_f;
    __nv_bfloat16* hsdst = dir ? g_hs_b : g_hs_f;
    int par = 0;

    float creg[16];
#pragma unroll
    for (int i = 0; i < 16; i++) creg[i] = 0.f;

    for (int s = 0; s < LSEQ; s++) {
        int t = dir ? (LSEQ - 1 - s) : s;
        const __nv_bfloat16* Ax = g_x + ((size_t)t * NB + brow) * XDIM;
        const __nv_bfloat16* Ah = g_h2[par] + ((size_t)dir * NB + brow) * HID;
        __nv_bfloat16* Hn = g_h2[par ^ 1] + (size_t)dir * NB * HID;

        wmma::fragment<wmma::accumulator, 16, 16, 16, float> acc[2][4];
#pragma unroll
        for (int i = 0; i < 2; i++)
#pragma unroll
            for (int j = 0; j < 4; j++)
                wmma::fill_fragment(acc[i][j], 0.f);

        auto load_x = [&](int buf, int k0) {
#pragma unroll
            for (int i = 0; i < 2; i++) {
                int cid = tid + i * 512;
                int row = cid >> 3, col = (cid & 7) * 8;
                cp16(&As[buf][row][col], Ax + (size_t)row * XDIM + k0 + col, true);
            }
#pragma unroll
            for (int i = 0; i < 4; i++) {
                int cid = tid + i * 512;
                int row = cid >> 5, col = (cid & 31) * 8;
                cp16(&Bs[buf][row][col], Wcat + (size_t)(k0 + row) * GATE + bcol + col, true);
            }
        };
        auto load_h = [&](int buf, int k0) {
#pragma unroll
            for (int i = 0; i < 2; i++) {
                int cid = tid + i * 512;
                int row = cid >> 3, col = (cid & 7) * 8;
                cp16(&As[buf][row][col], Ah + (size_t)row * HID + k0 + col, true);
            }
#pragma unroll
            for (int i = 0; i < 4; i++) {
                int cid = tid + i * 512;
                int row = cid >> 5, col = (cid & 31) * 8;
                cp16(&Bs[buf][row][col],
                     Wcat + (size_t)(XDIM + k0 + row) * GATE + bcol + col, true);
            }
        };
        auto mma_tile = [&](int buf) {
#pragma unroll
            for (int kk = 0; kk < 64; kk += 16) {
                wmma::fragment<wmma::matrix_a, 16, 16, 16, __nv_bfloat16, wmma::row_major> af[2];
#pragma unroll
                for (int i = 0; i < 2; i++)
                    wmma::load_matrix_sync(af[i], &As[buf][m0 + i * 16][kk], 72);
#pragma unroll
                for (int j = 0; j < 4; j++) {
                    wmma::fragment<wmma::matrix_b, 16, 16, 16, __nv_bfloat16, wmma::row_major> bfr;
                    wmma::load_matrix_sync(bfr, &Bs[buf][kk][n0 + j * 16], 264);
#pragma unroll
                    for (int i = 0; i < 2; i++)
                        wmma::mma_sync(acc[i][j], af[i], bfr, acc[i][j]);
                }
            }
        };

        // ---- x-phase: 4 tiles, 2-stage (buffers 0/1) ----
        load_x(0, 0);
        cp_commit();
        int buf = 0;
        for (int xt = 0; xt < 4; xt++) {
            if (xt + 1 < 4) { load_x(buf ^ 1, (xt + 1) * 64); cp_commit(); cp_wait1(); }
            else            { cp_wait0(); }
            __syncthreads();
            mma_tile(buf);
            __syncthreads();
            buf ^= 1;
        }

        // ---- h-phase: 8 tiles, 3-stage, single sync per tile ----
        if (s > 0) {
            bar_wait(&g_barA_gen, (unsigned)(s - 1));
            load_h(0, 0);
            cp_commit();
            load_h(1, 64);
            cp_commit();
            for (int ht = 0; ht < 8; ht++) {
                if (ht == 7) cp_wait0(); else cp_wait1();
                __syncthreads();
                if (ht + 2 < 8) { load_h((ht + 2) % 3, (ht + 2) * 64); cp_commit(); }
                mma_tile(ht % 3);
            }
            __syncthreads();   // all mma done before Cs staging (Cs overlaps buffers)
        }

        // ---- epilogue ----
#pragma unroll
        for (int i = 0; i < 2; i++)
#pragma unroll
            for (int j = 0; j < 4; j++)
                wmma::store_matrix_sync(&Cs[(m0 + i * 16) * 260 + n0 + j * 16],
                                        acc[i][j], 260, wmma::mem_row_major);
        __syncthreads();

#pragma unroll
        for (int it = 0; it < 16; it++) {
            int task = tid + it * 512;
            int r  = task >> 6;
            int jl = task & 63;
            int nb = brow + r;
            int u  = (bcol >> 2) + jl;
            float gi = Cs[r * 260 + jl * 4 + 0] + bias[u];
            float gf = Cs[r * 260 + jl * 4 + 1] + bias[512 + u];
            float gg = Cs[r * 260 + jl * 4 + 2] + bias[1024 + u];
            float go = Cs[r * 260 + jl * 4 + 3] + bias[1536 + u];
            float c = creg[it];
            c = fsig(gf) * c + fsig(gi) * ftanh(gg);
            float h = fsig(go) * ftanh(c);
            creg[it] = c;
            if (s == LSEQ - 1) g_c_enc[((size_t)dir * NB + nb) * HID + u] = c;
            __nv_bfloat16 hb = __float2bfloat16(h);
            hsdst[((size_t)t * NB + nb) * HID + u] = hb;
            Hn[(size_t)nb * HID + u] = hb;
        }

        if (s < LSEQ - 1)
            bar_arrive(&g_barA_cnt, &g_barA_gen, 128, (unsigned)s);
        par ^= 1;
    }
}

// ---------------- persistent Phase A: 3-stage pipe, single sync per tile ----------------
// smem: As[3][64][40] @0 (15360) | Bs[3][32][136] @15360 (26112); Cs [64][132] f32 union.
__global__ void __launch_bounds__(128) vlstm_persist(const float* __restrict__ v_b) {
    __shared__ __align__(16) char smu[41472];
    __nv_bfloat16 (*As)[64][40]  = reinterpret_cast<__nv_bfloat16(*)[64][40]>(smu);
    __nv_bfloat16 (*Bs)[32][136] = reinterpret_cast<__nv_bfloat16(*)[32][136]>(smu + 15360);
    float* Cs = reinterpret_cast<float*>(smu);

    int tid = threadIdx.x, warp = tid >> 5;
    int m0 = (warp & 1) * 32, n0 = (warp >> 1) * 64;
    int bid = blockIdx.x;
    int rt = bid >> 5, ct = bid & 31;
    int brow = rt * 64, bcol = ct * 128;

    float creg[16];
    bool cinit = false;

    for (int t = 0; t < TDEC - 1; t++) {
        int par = t & 1;
        const __nv_bfloat16* A = g_hdec_bf + (size_t)par * BATCH * EH;
        __nv_bfloat16* hout = g_hdec_bf + (size_t)(par ^ 1) * BATCH * EH;

        wmma::fragment<wmma::accumulator, 16, 16, 16, float> acc[2][4];
#pragma unroll
        for (int i = 0; i < 2; i++)
#pragma unroll
            for (int j = 0; j < 4; j++)
                wmma::fill_fragment(acc[i][j], 0.f);

        auto loadB = [&](int buf, int k0) {
#pragma unroll
            for (int i = 0; i < 4; i++) {
                int cid = tid + i * 128;
                int row = cid >> 4, col = (cid & 15) * 8;
                cp16(&Bs[buf][row][col], g_vWh_bf + (size_t)(k0 + row) * VG + bcol + col, true);
            }
        };
        auto loadA = [&](int buf, int k0) {
#pragma unroll
            for (int i = 0; i < 2; i++) {
                int cid = tid + i * 128;
                int row = cid >> 2, col = (cid & 3) * 8;
                cp16(&As[buf][row][col], A + (size_t)(brow + row) * EH + k0 + col, true);
            }
        };

        // prologue: B0 prefetch (h-independent) | barrier | A0, AB1
        loadB(0, 0);
        cp_commit();                               // g0
        if (!cinit) {
#pragma unroll
            for (int it = 0; it < 16; it++) {
                int task = tid + it * 128;
                int r = task >> 5, ju = task & 31;
                creg[it] = g_c_dec[(size_t)(brow + r) * EH + (bcol >> 2) + ju];
            }
            cinit = true;
        }
        if (t > 0) bar_wait(&g_barB_gen, (unsigned)(t - 1));
        loadA(0, 0);
        cp_commit();                               // g1
        loadA(1, 32); loadB(1, 32);
        cp_commit();                               // g2

        for (int kt = 0; kt < 32; kt++) {
            if (kt == 31) cp_wait0(); else cp_wait1();
            __syncthreads();
            if (kt + 2 < 32) {
                loadA((kt + 2) % 3, (kt + 2) * 32);
                loadB((kt + 2) % 3, (kt + 2) * 32);
                cp_commit();
            }
            int buf = kt % 3;
#pragma unroll
            for (int kk = 0; kk < 32; kk += 16) {
                wmma::fragment<wmma::matrix_a, 16, 16, 16, __nv_bfloat16, wmma::row_major> af[2];
#pragma unroll
                for (int i = 0; i < 2; i++)
                    wmma::load_matrix_sync(af[i], &As[buf][m0 + i * 16][kk], 40);
#pragma unroll
                for (int j = 0; j < 4; j++) {
                    wmma::fragment<wmma::matrix_b, 16, 16, 16, __nv_bfloat16, wmma::row_major> bfr;
                    wmma::load_matrix_sync(bfr, &Bs[buf][kk][n0 + j * 16], 136);
#pragma unroll
                    for (int i = 0; i < 2; i++)
                        wmma::mma_sync(acc[i][j], af[i], bfr, acc[i][j]);
                }
            }
        }
        __syncthreads();   // all mma done before Cs staging

#pragma unroll
        for (int i = 0; i < 2; i++)
#pragma unroll
            for (int j = 0; j < 4; j++)
                wmma::store_matrix_sync(&Cs[(m0 + i * 16) * 132 + n0 + j * 16], acc[i][j], 132,
                                        wmma::mem_row_major);
        __syncthreads();

        const float* xg = g_vXWi + (size_t)t * VG;
#pragma unroll
        for (int it = 0; it < 16; it++) {
            int task = tid + it * 128;
            int r = task >> 5, ju = task & 31;
            int b = brow + r;
            int u = (bcol >> 2) + ju;
            float gi = Cs[r * 132 + ju * 4 + 0] + xg[(u << 2) + 0] + v_b[u];
            float gf = Cs[r * 132 + ju * 4 + 1] + xg[(u << 2) + 1] + v_b[EH + u];
            float gg = Cs[r * 132 + ju * 4 + 2] + xg[(u << 2) + 2] + v_b[2 * EH + u];
            float go = Cs[r * 132 + ju * 4 + 3] + xg[(u << 2) + 3] + v_b[3 * EH + u];
            float c = creg[it];
            c = fsig(gf) * c + fsig(gi) * ftanh(gg);
            float h = fsig(go) * ftanh(c);
            creg[it] = c;
            size_t ci = (size_t)b * EH + u;
            __nv_bfloat16 hb = __float2bfloat16(h);
            hout[ci] = hb;
            g_feat[((size_t)(t + 1) * BATCH + b) * 2048 + u] = hb;
        }

        if (t < TDEC - 2)
            bar_arrive(&g_barB_cnt, &g_barB_gen, 128, (unsigned)t);
    }
}

// ---------------- setup kernels ----------------
__global__ void k_embed(const int* __restrict__ exs, const int* __restrict__ cls,
                        const float* __restrict__ E) {
    int idx = blockIdx.x * blockDim.x + threadIdx.x;
    int j  = idx & (XDIM - 1);
    int tn = idx >> 8;
    int tok = (j < IO_EMB) ? exs[tn] : cls[tn];
    int jj  = (j < IO_EMB) ? j : j - IO_EMB;
    g_x[idx] = __float2bfloat16(E[tok * IO_EMB + jj]);
}

__global__ void k_wcat(const float* __restrict__ Wi_f, const float* __restrict__ Wh_f,
                       const float* __restrict__ Wi_b, const float* __restrict__ Wh_b) {
    int idx = blockIdx.x * blockDim.x + threadIdx.x;   // 2*KCAT*GATE
    int dir = idx / (KCAT * GATE);
    int r   = idx - dir * (KCAT * GATE);
    int k   = r / GATE;
    int n   = r - k * GATE;
    int u = n >> 2, g = n & 3;
    int col = g * 512 + u;
    const float* src;
    int ks;
    if (k < XDIM) { src = dir ? Wi_b : Wi_f; ks = k; }
    else          { src = dir ? Wh_b : Wh_f; ks = k - XDIM; }
    g_Wcat[idx] = __float2bfloat16(src[ks * GATE + col]);
}

__global__ void k_init() {
    if (blockIdx.x == 0 && threadIdx.x == 0) {
        g_barA_cnt = 0u; g_barA_gen = 0u;
    }
}

// ---------------- pool final encoder states -> decoder init ----------------
__global__ void k_pool() {
    int idx = blockIdx.x * blockDim.x + threadIdx.x;   // BATCH*EH
    int b = idx >> 10;
    int e = idx & 1023;
    int ee = (e < 512) ? e : e - 512;
    float hm = -1e30f, cm = -1e30f;
#pragma unroll
    for (int n = 0; n < 4; n++) {
        size_t off = (size_t)(b * 4 + n) * HID + ee;
        float hv = (e < 512) ? __bfloat162float(g_hs_f[(size_t)(LSEQ - 1) * NB * HID + off])
                             : __bfloat162float(g_hs_b[off]);
        float cv = (e < 512) ? g_c_enc[off] : g_c_enc[(size_t)NB * HID + off];
        hm = fmaxf(hm, hv);
        cm = fmaxf(cm, cv);
    }
    g_c_dec[idx] = cm;
    __nv_bfloat16 hb = __float2bfloat16(hm);
    g_hdec_bf[idx] = hb;
    g_feat[(size_t)b * 2048 + e] = hb;
    if (idx == 0) { g_barB_cnt = 0u; g_barB_gen = 0u; }
}

// ---------------- Phase C: all-timestep attention per (b,n), bf16 ctx out ----------------
#define ATTN_SMEM (64*1032*2 + 32*1024*2 + 32*72*4 + 32*64*2)
__global__ void __launch_bounds__(256) k_attn_all() {
    extern __shared__ char smc[];
    __nv_bfloat16* hsS = (__nv_bfloat16*)smc;
    __nv_bfloat16* qS  = (__nv_bfloat16*)(smc + 64 * 1032 * 2);
    float*         scS = (float*)(smc + 64 * 1032 * 2 + 32 * 1024 * 2);
    __nv_bfloat16* awS = (__nv_bfloat16*)(smc + 64 * 1032 * 2 + 32 * 1024 * 2 + 32 * 72 * 4);

    int nb = blockIdx.x;
    int b  = nb >> 2;
    int tid = threadIdx.x, lane = tid & 31, warp = tid >> 5;

    for (int c = tid; c < 64 * 128; c += 256) {
        int l = c >> 7, off = (c & 127) * 8;
        const __nv_bfloat16* src = (off < 512)
            ? g_hs_f + ((size_t)l * NB + nb) * HID + off
            : g_hs_b + ((size_t)l * NB + nb) * HID + (off - 512);
        *(uint4*)&hsS[l * 1032 + off] = *(const uint4*)src;
    }
    for (int c = tid; c < 32 * 512; c += 256) {
        int t = c >> 9, d2 = (c & 511) * 2;
        float2 f = *(const float2*)&g_q_all[((size_t)t * BATCH + b) * EH + d2];
        *(__nv_bfloat162*)&qS[t * 1024 + d2] = __float22bfloat162_rn(f);
    }
    __syncthreads();

    {
        int mi = warp >> 2, ni = warp & 3;
        wmma::fragment<wmma::accumulator, 16, 16, 16, float> acc;
        wmma::fill_fragment(acc, 0.f);
        for (int k = 0; k < 1024; k += 16) {
            wmma::fragment<wmma::matrix_a, 16, 16, 16, __nv_bfloat16, wmma::row_major> a;
            wmma::fragment<wmma::matrix_b, 16, 16, 16, __nv_bfloat16, wmma::col_major> bm;
            wmma::load_matrix_sync(a, qS + mi * 16 * 1024 + k, 1024);
            wmma::load_matrix_sync(bm, hsS + (ni * 16) * 1032 + k, 1032);
            wmma::mma_sync(acc, a, bm, acc);
        }
        wmma::store_matrix_sync(scS + mi * 16 * 72 + ni * 16, acc, 72, wmma::mem_row_major);
    }
    __syncthreads();

    for (int t = warp; t < 32; t += 8) {
        float s0 = scS[t * 72 + lane], s1 = scS[t * 72 + 32 + lane];
        float mx = fmaxf(s0, s1);
#pragma unroll
        for (int o = 16; o > 0; o >>= 1) mx = fmaxf(mx, __shfl_xor_sync(0xffffffffu, mx, o));
        float e0 = __expf(s0 - mx), e1 = __expf(s1 - mx);
        float sum = e0 + e1;
#pragma unroll
        for (int o = 16; o > 0; o >>= 1) sum += __shfl_xor_sync(0xffffffffu, sum, o);
        float inv = 1.f / sum;
        awS[t * 64 + lane]      = __float2bfloat16(e0 * inv);
        awS[t * 64 + 32 + lane] = __float2bfloat16(e1 * inv);
    }
    __syncthreads();

    {
        float* wsc = (float*)qS + warp * 1024;
        wmma::fragment<wmma::matrix_a, 16, 16, 16, __nv_bfloat16, wmma::row_major> a[2][4];
#pragma unroll
        for (int mi = 0; mi < 2; mi++)
#pragma unroll
            for (int kt = 0; kt < 4; kt++)
                wmma::load_matrix_sync(a[mi][kt], awS + mi * 16 * 64 + kt * 16, 64);
        for (int nt = 0; nt < 8; nt++) {
            int n0 = warp * 128 + nt * 16;
            wmma::fragment<wmma::accumulator, 16, 16, 16, float> acc[2];
            wmma::fill_fragment(acc[0], 0.f);
            wmma::fill_fragment(acc[1], 0.f);
#pragma unroll
            for (int kt = 0; kt < 4; kt++) {
                wmma::fragment<wmma::matrix_b, 16, 16, 16, __nv_bfloat16, wmma::row_major> bm;
                wmma::load_matrix_sync(bm, hsS + kt * 16 * 1032 + n0, 1032);
                wmma::mma_sync(acc[0], a[0][kt], bm, acc[0]);
                wmma::mma_sync(acc[1], a[1][kt], bm, acc[1]);
            }
            wmma::store_matrix_sync(wsc,       acc[0], 16, wmma::mem_row_major);
            wmma::store_matrix_sync(wsc + 256, acc[1], 16, wmma::mem_row_major);
            __syncwarp();
            {
                int tt = lane;
                const float* src = wsc + (tt >> 4) * 256 + (tt & 15) * 16;
                __nv_bfloat162 pk2[8];
#pragma unroll
                for (int h = 0; h < 8; h++)
                    pk2[h] = __float22bfloat162_rn(make_float2(src[h * 2], src[h * 2 + 1]));
                __nv_bfloat16* dst = g_ctx_bf + ((size_t)tt * NB + nb) * EH + n0;
                *(uint4*)dst       = *(uint4*)&pk2[0];
                *(uint4*)(dst + 8) = *(uint4*)&pk2[4];
            }
            __syncwarp();
        }
    }
}

// ---------------- Phase D ----------------
__global__ void k_ctxpool() {
    int idx = blockIdx.x * blockDim.x + threadIdx.x;
    int d  = idx & 1023;
    int tb = idx >> 10;
    int b  = tb & 255, t = tb >> 8;
    const __nv_bfloat16* base = g_ctx_bf + ((size_t)t * NB + b * 4) * EH + d;
    float m = fmaxf(
        fmaxf(__bfloat162float(base[0]), __bfloat162float(base[EH])),
        fmaxf(__bfloat162float(base[2 * EH]), __bfloat162float(base[3 * EH])));
    g_feat[(size_t)tb * 2048 + 1024 + d] = __float2bfloat16(m);
}

__global__ void k_out(float* __restrict__ out) {
    int b = threadIdx.x;
    float s = 0.f;
    for (int t = 0; t < TDEC; t++) s += g_nll[t * BATCH + b];
    out[b] = s;
}

// ---------------- host orchestration ----------------
extern "C" void kernel_launch(void* const* d_in, const int* in_sizes, int n_in,
                              void* d_out, int out_size) {
    const int*   exs     = (const int*)  d_in[0];
    const int*   cls     = (const int*)  d_in[1];
    const float* E       = (const float*)d_in[2];
    const float* Wi_f    = (const float*)d_in[3];
    const float* Wh_f    = (const float*)d_in[4];
    const float* b_f     = (const float*)d_in[5];
    const float* Wi_b    = (const float*)d_in[6];
    const float* Wh_b    = (const float*)d_in[7];
    const float* b_b     = (const float*)d_in[8];
    const float* W_attn  = (const float*)d_in[9];
    const float* W_comp  = (const float*)d_in[10];
    const float* b_comp  = (const float*)d_in[11];
    const float* v_Wi    = (const float*)d_in[12];
    const float* v_Wh    = (const float*)d_in[13];
    const float* v_b     = (const float*)d_in[14];
    const float* field   = (const float*)d_in[15];
    const int*   actions = (const int*)  d_in[16];
    float* out = (float*)d_out;

    cudaFuncSetAttribute(enc_persist, cudaFuncAttributeMaxDynamicSharedMemorySize, ENC_DYN);
    cudaFuncSetAttribute(k_attn_all, cudaFuncAttributeMaxDynamicSharedMemorySize, ATTN_SMEM);

    __nv_bfloat16 *p_feat, *p_Wattn_bf;
    float *p_q_all;
    cudaGetSymbolAddress((void**)&p_feat, g_feat);
    cudaGetSymbolAddress((void**)&p_Wattn_bf, g_Wattn_bf);
    cudaGetSymbolAddress((void**)&p_q_all, g_q_all);

    // ---- setup ----
    k_embed<<<(LSEQ * NB * XDIM) / 256, 256>>>(exs, cls, E);
    k_wcat<<<(2 * KCAT * GATE) / 256, 256>>>(Wi_f, Wh_f, Wi_b, Wh_b);
    k_init<<<1, 32>>>();

    // ---- encoder (workers) + conversions/vXWi (helper blocks) ----
    enc_persist<<<148, 512, ENC_DYN>>>(b_f, b_b, W_attn, v_Wi, v_Wh, field, W_comp);

    // ---- decoder init ----
    k_pool<<<(BATCH * EH) / 256, 256>>>();

    // ---- Phase A: persistent v-LSTM recurrence (31 steps) ----
    vlstm_persist<<<128, 128>>>(v_b);

    // ---- Phase B: q_all = h_hist @ W_attn ----
    gemm_bf16<<<dim3(EH / BN, TB / BM), 256>>>(
        p_feat, p_Wattn_bf, p_q_all, TB, EH, EH, 2048, EH, EH);

    // ---- Phase C ----
    k_attn_all<<<NB, 256, ATTN_SMEM>>>();

    // ---- Phase D ----
    k_ctxpool<<<(TDEC * BATCH * EH) / 256, 256>>>();
    gemm_cls<<<dim3(1, TB / 64), 128>>>(b_comp, actions);
    k_out<<<1, BATCH>>>(out);
}

// round 17
// speedup vs baseline: 1.0390x; 1.0390x over previous
#include <cuda_runtime.h>
#include <cuda_bf16.h>
#include <mma.h>
#include <cstdint>
#include <cstddef>
using namespace nvcuda;

// ---------------- problem constants ----------------
#define LSEQ   64
#define BATCH  256
#define NIO    4
#define NB     1024      // BATCH*NIO
#define IO_EMB 128
#define XDIM   256       // 2*IO_EMB
#define HID    512       // IO_HID
#define GATE   2048      // 4*HID
#define KCAT   768       // XDIM + HID
#define EH     1024      // ENC_HID
#define VG     4096      // 4*EH
#define TDEC   32
#define NPROD  64
#define TB     (TDEC * BATCH)   // 8192

// ---------------- device scratch (static, no allocs) ----------------
__device__ __nv_bfloat16 g_x[(size_t)LSEQ * NB * XDIM];
__device__ __nv_bfloat16 g_h2[2][(size_t)2 * NB * HID];      // encoder h parity buffers
__device__ __nv_bfloat16 g_Wcat[2 * KCAT * GATE];            // interleaved: col = 4*u + gate
__device__ float g_c_enc[2 * NB * HID];
__device__ __nv_bfloat16 g_hs_f[(size_t)LSEQ * NB * HID];
__device__ __nv_bfloat16 g_hs_b[(size_t)LSEQ * NB * HID];
__device__ float g_c_dec[BATCH * EH];
__device__ __nv_bfloat16 g_hdec_bf[2 * BATCH * EH];          // parity double buffer
__device__ __nv_bfloat16 g_feat[(size_t)TB * 2048];          // [t*256+b][ h(1024) | ctxp(1024) ]
__device__ float g_q_all[(size_t)TB * EH];
__device__ __nv_bfloat16 g_ctx_bf[(size_t)TDEC * NB * EH];   // bf16 ctx
__device__ float g_vXWi[TDEC * VG];                          // interleaved gates
__device__ __nv_bfloat16 g_Wattn_bf[EH * EH];
__device__ __nv_bfloat16 g_vWi_bf[EH * VG];                  // interleaved
__device__ __nv_bfloat16 g_vWh_bf[EH * VG];                  // interleaved
__device__ __nv_bfloat16 g_field_bf[TDEC * EH];
__device__ __nv_bfloat16 g_Wcls_bf[2048 * NPROD];
__device__ float g_nll[TB];

// grid-barrier state (reset every call in k_init / k_pool)
__device__ unsigned g_barA_cnt, g_barA_gen;
__device__ unsigned g_barB_cnt, g_barB_gen;

// fast activations
__device__ __forceinline__ float ftanh(float x) {
    float y;
    asm("tanh.approx.f32 %0, %1;" : "=f"(y) : "f"(x));
    return y;
}
__device__ __forceinline__ float fsig(float x) { return fmaf(ftanh(x * 0.5f), 0.5f, 0.5f); }

// split grid barrier
__device__ __forceinline__ void bar_arrive(unsigned* cnt, unsigned* gen, unsigned nblk,
                                           unsigned my) {
    __syncthreads();
    if (threadIdx.x == 0) {
        __threadfence();
        unsigned old = atomicAdd(cnt, 1u);
        if (old == nblk - 1) {
            *cnt = 0u;
            __threadfence();
            atomicExch(gen, my + 1u);
        }
    }
}
__device__ __forceinline__ void bar_wait(unsigned* gen, unsigned my) {
    if (threadIdx.x == 0) {
        while (atomicAdd(gen, 0u) <= my) { }
        __threadfence();
    }
    __syncthreads();
}

// ---------------- cp.async helpers ----------------
__device__ __forceinline__ void cp16(void* dst, const void* src, bool valid) {
    unsigned int d = (unsigned int)__cvta_generic_to_shared(dst);
    int sz = valid ? 16 : 0;
    asm volatile("cp.async.cg.shared.global [%0], [%1], 16, %2;" :: "r"(d), "l"(src), "r"(sz));
}
__device__ __forceinline__ void cp_commit() { asm volatile("cp.async.commit_group;"); }
__device__ __forceinline__ void cp_wait1()  { asm volatile("cp.async.wait_group 1;"); }
__device__ __forceinline__ void cp_wait0()  { asm volatile("cp.async.wait_group 0;"); }

#define BM 128
#define BN 128
#define BK 32

// ---------------- 128x128 bf16 tensor-core GEMM ----------------
__global__ void __launch_bounds__(256) gemm_bf16(
    const __nv_bfloat16* __restrict__ A, const __nv_bfloat16* __restrict__ B,
    float* __restrict__ C, int M, int N, int K, int lda, int ldb, int ldc)
{
    __shared__ __nv_bfloat16 As[2][BM][40];
    __shared__ __nv_bfloat16 Bs[2][BK][136];

    int tid  = threadIdx.x;
    int warp = tid >> 5;
    int wr = warp >> 1, wc = warp & 1;
    int brow = blockIdx.y * BM, bcol = blockIdx.x * BN;
    int m0 = wr * 32, n0 = wc * 64;

    wmma::fragment<wmma::accumulator, 16, 16, 16, float> acc[2][4];
#pragma unroll
    for (int i = 0; i < 2; i++)
#pragma unroll
        for (int j = 0; j < 4; j++)
            wmma::fill_fragment(acc[i][j], 0.f);

    int nk = K / BK;

    auto load_tile = [&](int buf, int k0) {
#pragma unroll
        for (int i = 0; i < 2; i++) {
            int cid = tid + i * 256;
            int row = cid >> 2;
            int col = (cid & 3) * 8;
            const __nv_bfloat16* src = A + (size_t)(brow + row) * lda + k0 + col;
            bool v = (brow + row) < M;
            cp16(&As[buf][row][col], v ? (const void*)src : (const void*)A, v);
        }
#pragma unroll
        for (int i = 0; i < 2; i++) {
            int cid = tid + i * 256;
            int row = cid >> 4;
            int col = (cid & 15) * 8;
            cp16(&Bs[buf][row][col], B + (size_t)(k0 + row) * ldb + bcol + col, true);
        }
    };

    load_tile(0, 0);
    cp_commit();

    int buf = 0;
    for (int kt = 0; kt < nk; kt++) {
        if (kt + 1 < nk) { load_tile(buf ^ 1, (kt + 1) * BK); cp_commit(); cp_wait1(); }
        else             { cp_wait0(); }
        __syncthreads();
#pragma unroll
        for (int kk = 0; kk < BK; kk += 16) {
            wmma::fragment<wmma::matrix_a, 16, 16, 16, __nv_bfloat16, wmma::row_major> af[2];
            wmma::fragment<wmma::matrix_b, 16, 16, 16, __nv_bfloat16, wmma::row_major> bfr[4];
#pragma unroll
            for (int i = 0; i < 2; i++)
                wmma::load_matrix_sync(af[i], &As[buf][m0 + i * 16][kk], 40);
#pragma unroll
            for (int j = 0; j < 4; j++)
                wmma::load_matrix_sync(bfr[j], &Bs[buf][kk][n0 + j * 16], 136);
#pragma unroll
            for (int i = 0; i < 2; i++)
#pragma unroll
                for (int j = 0; j < 4; j++)
                    wmma::mma_sync(acc[i][j], af[i], bfr[j], acc[i][j]);
        }
        __syncthreads();
        buf ^= 1;
    }

#pragma unroll
    for (int i = 0; i < 2; i++) {
        int gm = brow + m0 + i * 16;
        if (gm >= M) continue;
#pragma unroll
        for (int j = 0; j < 4; j++)
            wmma::store_matrix_sync(&C[(size_t)gm * ldc + bcol + n0 + j * 16],
                                    acc[i][j], ldc, wmma::mem_row_major);
    }
}

// ---------------- fused classifier GEMM + NLL ----------------
__global__ void __launch_bounds__(128) gemm_cls(
    const float* __restrict__ b_comp, const int* __restrict__ actions)
{
    __shared__ __align__(16) char smu[19456];
    __nv_bfloat16 (*As)[64][40] = reinterpret_cast<__nv_bfloat16(*)[64][40]>(smu);
    __nv_bfloat16 (*Bs)[32][72] = reinterpret_cast<__nv_bfloat16(*)[32][72]>(smu + 10240);
    float* Cs = reinterpret_cast<float*>(smu);   // [64][68] (union, post-loop)

    int tid = threadIdx.x, warp = tid >> 5;
    int m0 = (warp & 1) * 32, n0 = (warp >> 1) * 32;
    int brow = blockIdx.y * 64;
    const __nv_bfloat16* A = g_feat + (size_t)brow * 2048;

    wmma::fragment<wmma::accumulator, 16, 16, 16, float> acc[2][2];
#pragma unroll
    for (int i = 0; i < 2; i++)
#pragma unroll
        for (int j = 0; j < 2; j++)
            wmma::fill_fragment(acc[i][j], 0.f);

    auto load_tile = [&](int buf, int k0) {
#pragma unroll
        for (int i = 0; i < 2; i++) {
            int cid = tid + i * 128;
            int row = cid >> 2, col = (cid & 3) * 8;
            cp16(&As[buf][row][col], A + (size_t)row * 2048 + k0 + col, true);
        }
#pragma unroll
        for (int i = 0; i < 2; i++) {
            int cid = tid + i * 128;
            int row = cid >> 3, col = (cid & 7) * 8;
            cp16(&Bs[buf][row][col], g_Wcls_bf + (size_t)(k0 + row) * NPROD + col, true);
        }
    };

    load_tile(0, 0);
    cp_commit();
    int buf = 0;
    for (int kt = 0; kt < 64; kt++) {
        if (kt + 1 < 64) { load_tile(buf ^ 1, (kt + 1) * 32); cp_commit(); cp_wait1(); }
        else             { cp_wait0(); }
        __syncthreads();
#pragma unroll
        for (int kk = 0; kk < 32; kk += 16) {
            wmma::fragment<wmma::matrix_a, 16, 16, 16, __nv_bfloat16, wmma::row_major> af[2];
            wmma::fragment<wmma::matrix_b, 16, 16, 16, __nv_bfloat16, wmma::row_major> bfr[2];
#pragma unroll
            for (int i = 0; i < 2; i++)
                wmma::load_matrix_sync(af[i], &As[buf][m0 + i * 16][kk], 40);
#pragma unroll
            for (int j = 0; j < 2; j++)
                wmma::load_matrix_sync(bfr[j], &Bs[buf][kk][n0 + j * 16], 72);
#pragma unroll
            for (int i = 0; i < 2; i++)
#pragma unroll
                for (int j = 0; j < 2; j++)
                    wmma::mma_sync(acc[i][j], af[i], bfr[j], acc[i][j]);
        }
        __syncthreads();
        buf ^= 1;
    }

#pragma unroll
    for (int i = 0; i < 2; i++)
#pragma unroll
        for (int j = 0; j < 2; j++)
            wmma::store_matrix_sync(&Cs[(m0 + i * 16) * 68 + n0 + j * 16], acc[i][j], 68,
                                    wmma::mem_row_major);
    __syncthreads();

    if (tid < 64) {
        int row = tid;
        float mx = -1e30f;
        for (int j = 0; j < NPROD; j++)
            mx = fmaxf(mx, Cs[row * 68 + j] + b_comp[j]);
        float sum = 0.f;
        for (int j = 0; j < NPROD; j++)
            sum += __expf(Cs[row * 68 + j] + b_comp[j] - mx);
        int tb = brow + row;
        int t = tb >> 8, b = tb & 255;
        int a = actions[b * TDEC + t];
        g_nll[tb] = mx + __logf(sum) - (Cs[row * 68 + a] + b_comp[a]);
    }
}

// ---------------- persistent encoder: 2 blocks/SM (enforced) + helper blocks ----------------
// 276 blocks: 0-255 = 2 dirs x 8 row-tiles(128) x 16 col-tiles(128), 256 threads;
//             256-275 = decoder-weight conversion helpers (exit early).
// __launch_bounds__(256, 2): <=128 regs, 2 blocks/SM guaranteed -> all 276 co-resident.
// smem: As[2][128][72] @0 (36864) | Bs[2][64][136] @36864 (34816) = 71680; Cs union.
#define ENC_DYN 71680
__global__ void __launch_bounds__(256, 2) enc_persist(
    const float* __restrict__ b_f, const float* __restrict__ b_b,
    const float* __restrict__ W_attn, const float* __restrict__ v_Wi,
    const float* __restrict__ v_Wh, const float* __restrict__ field,
    const float* __restrict__ W_comp)
{
    extern __shared__ __align__(16) char dyn[];
    int tid = threadIdx.x;
    int bid = blockIdx.x;

    if (bid >= 256) {   // helper: decoder weight conversions, hidden under encoder
        const int NH = 20 * 256;
        int hid = (bid - 256) * 256 + tid;
        for (int idx = hid; idx < EH * VG; idx += NH) {
            int k = idx >> 12, n = idx & 4095;
            int u = n >> 2, g = n & 3;
            g_vWi_bf[idx] = __float2bfloat16(v_Wi[k * VG + g * 1024 + u]);
            g_vWh_bf[idx] = __float2bfloat16(v_Wh[k * VG + g * 1024 + u]);
        }
        for (int idx = hid; idx < EH * EH; idx += NH)
            g_Wattn_bf[idx] = __float2bfloat16(W_attn[idx]);
        for (int idx = hid; idx < TDEC * EH; idx += NH)
            g_field_bf[idx] = __float2bfloat16(field[idx]);
        for (int idx = hid; idx < 2048 * NPROD; idx += NH)
            g_Wcls_bf[idx] = __float2bfloat16(W_comp[idx]);
        return;
    }

    __nv_bfloat16 (*As)[128][72] = reinterpret_cast<__nv_bfloat16(*)[128][72]>(dyn);
    __nv_bfloat16 (*Bs)[64][136] = reinterpret_cast<__nv_bfloat16(*)[64][136]>(dyn + 36864);
    float* Cs = reinterpret_cast<float*>(dyn);           // [128][132] (union)

    int warp = tid >> 5;
    int wr = warp >> 1, wc = warp & 1;
    int dir = bid >> 7;
    int rt = (bid >> 4) & 7, ct = bid & 15;
    int brow = rt * 128, bcol = ct * 128;
    int m0 = wr * 32, n0 = wc * 64;

    const __nv_bfloat16* Wcat = g_Wcat + (size_t)dir * KCAT * GATE;
    const float* bias = dir ? b_b : b_f;
    __nv_bfloat16* hsdst = dir ? g_hs_b : g_hs_f;
    int par = 0;

    float creg[16];
#pragma unroll
    for (int i = 0; i < 16; i++) creg[i] = 0.f;

    for (int s = 0; s < LSEQ; s++) {
        int t = dir ? (LSEQ - 1 - s) : s;
        const __nv_bfloat16* Ax = g_x + ((size_t)t * NB + brow) * XDIM;
        const __nv_bfloat16* Ah = g_h2[par] + ((size_t)dir * NB + brow) * HID;
        __nv_bfloat16* Hn = g_h2[par ^ 1] + (size_t)dir * NB * HID;

        wmma::fragment<wmma::accumulator, 16, 16, 16, float> acc[2][4];
#pragma unroll
        for (int i = 0; i < 2; i++)
#pragma unroll
            for (int j = 0; j < 4; j++)
                wmma::fill_fragment(acc[i][j], 0.f);

        auto load_x = [&](int buf, int k0) {
#pragma unroll
            for (int i = 0; i < 4; i++) {      // A: 128x64 = 1024 chunks
                int cid = tid + i * 256;
                int row = cid >> 3, col = (cid & 7) * 8;
                cp16(&As[buf][row][col], Ax + (size_t)row * XDIM + k0 + col, true);
            }
#pragma unroll
            for (int i = 0; i < 4; i++) {      // B: 64x128 = 1024 chunks
                int cid = tid + i * 256;
                int row = cid >> 4, col = (cid & 15) * 8;
                cp16(&Bs[buf][row][col], Wcat + (size_t)(k0 + row) * GATE + bcol + col, true);
            }
        };
        auto load_h = [&](int buf, int k0) {
#pragma unroll
            for (int i = 0; i < 4; i++) {
                int cid = tid + i * 256;
                int row = cid >> 3, col = (cid & 7) * 8;
                cp16(&As[buf][row][col], Ah + (size_t)row * HID + k0 + col, true);
            }
#pragma unroll
            for (int i = 0; i < 4; i++) {
                int cid = tid + i * 256;
                int row = cid >> 4, col = (cid & 15) * 8;
                cp16(&Bs[buf][row][col],
                     Wcat + (size_t)(XDIM + k0 + row) * GATE + bcol + col, true);
            }
        };
        auto mma_tile = [&](int buf) {
#pragma unroll
            for (int kk = 0; kk < 64; kk += 16) {
                wmma::fragment<wmma::matrix_a, 16, 16, 16, __nv_bfloat16, wmma::row_major> af[2];
#pragma unroll
                for (int i = 0; i < 2; i++)
                    wmma::load_matrix_sync(af[i], &As[buf][m0 + i * 16][kk], 72);
#pragma unroll
                for (int j = 0; j < 4; j++) {
                    wmma::fragment<wmma::matrix_b, 16, 16, 16, __nv_bfloat16, wmma::row_major> bfr;
                    wmma::load_matrix_sync(bfr, &Bs[buf][kk][n0 + j * 16], 136);
#pragma unroll
                    for (int i = 0; i < 2; i++)
                        wmma::mma_sync(acc[i][j], af[i], bfr, acc[i][j]);
                }
            }
        };

        // ---- x-phase: 4 tiles ----
        load_x(0, 0);
        cp_commit();
        int buf = 0;
        for (int xt = 0; xt < 4; xt++) {
            if (xt + 1 < 4) { load_x(buf ^ 1, (xt + 1) * 64); cp_commit(); cp_wait1(); }
            else            { cp_wait0(); }
            __syncthreads();
            mma_tile(buf);
            __syncthreads();
            buf ^= 1;
        }

        // ---- h-phase (skip at s=0) ----
        if (s > 0) {
            bar_wait(&g_barA_gen, (unsigned)(s - 1));
            load_h(buf, 0);
            cp_commit();
            for (int ht = 0; ht < 8; ht++) {
                if (ht + 1 < 8) { load_h(buf ^ 1, (ht + 1) * 64); cp_commit(); cp_wait1(); }
                else            { cp_wait0(); }
                __syncthreads();
                mma_tile(buf);
                __syncthreads();
                buf ^= 1;
            }
        }

        // ---- epilogue: stage gates, LSTM pointwise (c in registers) ----
#pragma unroll
        for (int i = 0; i < 2; i++)
#pragma unroll
            for (int j = 0; j < 4; j++)
                wmma::store_matrix_sync(&Cs[(m0 + i * 16) * 132 + n0 + j * 16],
                                        acc[i][j], 132, wmma::mem_row_major);
        __syncthreads();

#pragma unroll
        for (int it = 0; it < 16; it++) {
            int task = tid + it * 256;
            int r  = task >> 5;
            int jl = task & 31;
            int nb = brow + r;
            int u  = (bcol >> 2) + jl;
            float gi = Cs[r * 132 + jl * 4 + 0] + bias[u];
            float gf = Cs[r * 132 + jl * 4 + 1] + bias[512 + u];
            float gg = Cs[r * 132 + jl * 4 + 2] + bias[1024 + u];
            float go = Cs[r * 132 + jl * 4 + 3] + bias[1536 + u];
            float c = creg[it];
            c = fsig(gf) * c + fsig(gi) * ftanh(gg);
            float h = fsig(go) * ftanh(c);
            creg[it] = c;
            if (s == LSEQ - 1) g_c_enc[((size_t)dir * NB + nb) * HID + u] = c;
            __nv_bfloat16 hb = __float2bfloat16(h);
            hsdst[((size_t)t * NB + nb) * HID + u] = hb;
            Hn[(size_t)nb * HID + u] = hb;
        }

        if (s < LSEQ - 1)
            bar_arrive(&g_barA_cnt, &g_barA_gen, 256, (unsigned)s);
        par ^= 1;
    }
}

// ---------------- persistent Phase A: 31 fused v-LSTM steps ----------------
__global__ void __launch_bounds__(128) vlstm_persist(const float* __restrict__ v_b) {
    __shared__ __align__(16) char smu[64 * 132 * 4];
    __nv_bfloat16 (*As)[64][40]  = reinterpret_cast<__nv_bfloat16(*)[64][40]>(smu);
    __nv_bfloat16 (*Bs)[32][136] = reinterpret_cast<__nv_bfloat16(*)[32][136]>(smu + 10240);
    float* Cs = reinterpret_cast<float*>(smu);

    int tid = threadIdx.x, warp = tid >> 5;
    int m0 = (warp & 1) * 32, n0 = (warp >> 1) * 64;
    int bid = blockIdx.x;
    int rt = bid >> 5, ct = bid & 31;
    int brow = rt * 64, bcol = ct * 128;

    float creg[16];
    bool cinit = false;

    for (int t = 0; t < TDEC - 1; t++) {
        int par = t & 1;
        const __nv_bfloat16* A = g_hdec_bf + (size_t)par * BATCH * EH;
        __nv_bfloat16* hout = g_hdec_bf + (size_t)(par ^ 1) * BATCH * EH;

        wmma::fragment<wmma::accumulator, 16, 16, 16, float> acc[2][4];
#pragma unroll
        for (int i = 0; i < 2; i++)
#pragma unroll
            for (int j = 0; j < 4; j++)
                wmma::fill_fragment(acc[i][j], 0.f);

        auto loadB = [&](int buf, int k0) {
#pragma unroll
            for (int i = 0; i < 4; i++) {
                int cid = tid + i * 128;
                int row = cid >> 4, col = (cid & 15) * 8;
                cp16(&Bs[buf][row][col], g_vWh_bf + (size_t)(k0 + row) * VG + bcol + col, true);
            }
        };
        auto loadA = [&](int buf, int k0) {
#pragma unroll
            for (int i = 0; i < 2; i++) {
                int cid = tid + i * 128;
                int row = cid >> 2, col = (cid & 3) * 8;
                cp16(&As[buf][row][col], A + (size_t)(brow + row) * EH + k0 + col, true);
            }
        };

        loadB(0, 0);
        cp_commit();
        if (t > 0) bar_wait(&g_barB_gen, (unsigned)(t - 1));
        loadA(0, 0);
        cp_commit();

        if (!cinit) {
#pragma unroll
            for (int it = 0; it < 16; it++) {
                int task = tid + it * 128;
                int r = task >> 5, ju = task & 31;
                creg[it] = g_c_dec[(size_t)(brow + r) * EH + (bcol >> 2) + ju];
            }
            cinit = true;
        }

        int buf = 0;
        for (int kt = 0; kt < EH / 32; kt++) {
            if (kt + 1 < EH / 32) {
                loadA(buf ^ 1, (kt + 1) * 32);
                loadB(buf ^ 1, (kt + 1) * 32);
                cp_commit();
                cp_wait1();
            } else {
                cp_wait0();
            }
            __syncthreads();
#pragma unroll
            for (int kk = 0; kk < 32; kk += 16) {
                wmma::fragment<wmma::matrix_a, 16, 16, 16, __nv_bfloat16, wmma::row_major> af[2];
#pragma unroll
                for (int i = 0; i < 2; i++)
                    wmma::load_matrix_sync(af[i], &As[buf][m0 + i * 16][kk], 40);
#pragma unroll
                for (int j = 0; j < 4; j++) {
                    wmma::fragment<wmma::matrix_b, 16, 16, 16, __nv_bfloat16, wmma::row_major> bfr;
                    wmma::load_matrix_sync(bfr, &Bs[buf][kk][n0 + j * 16], 136);
#pragma unroll
                    for (int i = 0; i < 2; i++)
                        wmma::mma_sync(acc[i][j], af[i], bfr, acc[i][j]);
                }
            }
            __syncthreads();
            buf ^= 1;
        }

#pragma unroll
        for (int i = 0; i < 2; i++)
#pragma unroll
            for (int j = 0; j < 4; j++)
                wmma::store_matrix_sync(&Cs[(m0 + i * 16) * 132 + n0 + j * 16], acc[i][j], 132,
                                        wmma::mem_row_major);
        __syncthreads();

        const float* xg = g_vXWi + (size_t)t * VG;
#pragma unroll
        for (int it = 0; it < 16; it++) {
            int task = tid + it * 128;
            int r = task >> 5, ju = task & 31;
            int b = brow + r;
            int u = (bcol >> 2) + ju;
            float gi = Cs[r * 132 + ju * 4 + 0] + xg[(u << 2) + 0] + v_b[u];
            float gf = Cs[r * 132 + ju * 4 + 1] + xg[(u << 2) + 1] + v_b[EH + u];
            float gg = Cs[r * 132 + ju * 4 + 2] + xg[(u << 2) + 2] + v_b[2 * EH + u];
            float go = Cs[r * 132 + ju * 4 + 3] + xg[(u << 2) + 3] + v_b[3 * EH + u];
            float c = creg[it];
            c = fsig(gf) * c + fsig(gi) * ftanh(gg);
            float h = fsig(go) * ftanh(c);
            creg[it] = c;
            size_t ci = (size_t)b * EH + u;
            __nv_bfloat16 hb = __float2bfloat16(h);
            hout[ci] = hb;
            g_feat[((size_t)(t + 1) * BATCH + b) * 2048 + u] = hb;
        }

        if (t < TDEC - 2)
            bar_arrive(&g_barB_cnt, &g_barB_gen, 128, (unsigned)t);
    }
}

// ---------------- setup kernels ----------------
__global__ void k_embed(const int* __restrict__ exs, const int* __restrict__ cls,
                        const float* __restrict__ E) {
    int idx = blockIdx.x * blockDim.x + threadIdx.x;
    int j  = idx & (XDIM - 1);
    int tn = idx >> 8;
    int tok = (j < IO_EMB) ? exs[tn] : cls[tn];
    int jj  = (j < IO_EMB) ? j : j - IO_EMB;
    g_x[idx] = __float2bfloat16(E[tok * IO_EMB + jj]);
}

__global__ void k_wcat(const float* __restrict__ Wi_f, const float* __restrict__ Wh_f,
                       const float* __restrict__ Wi_b, const float* __restrict__ Wh_b) {
    int idx = blockIdx.x * blockDim.x + threadIdx.x;   // 2*KCAT*GATE
    int dir = idx / (KCAT * GATE);
    int r   = idx - dir * (KCAT * GATE);
    int k   = r / GATE;
    int n   = r - k * GATE;
    int u = n >> 2, g = n & 3;
    int col = g * 512 + u;
    const float* src;
    int ks;
    if (k < XDIM) { src = dir ? Wi_b : Wi_f; ks = k; }
    else          { src = dir ? Wh_b : Wh_f; ks = k - XDIM; }
    g_Wcat[idx] = __float2bfloat16(src[ks * GATE + col]);
}

__global__ void k_init() {
    if (blockIdx.x == 0 && threadIdx.x == 0) {
        g_barA_cnt = 0u; g_barA_gen = 0u;
    }
}

// ---------------- pool final encoder states -> decoder init ----------------
__global__ void k_pool() {
    int idx = blockIdx.x * blockDim.x + threadIdx.x;   // BATCH*EH
    int b = idx >> 10;
    int e = idx & 1023;
    int ee = (e < 512) ? e : e - 512;
    float hm = -1e30f, cm = -1e30f;
#pragma unroll
    for (int n = 0; n < 4; n++) {
        size_t off = (size_t)(b * 4 + n) * HID + ee;
        float hv = (e < 512) ? __bfloat162float(g_hs_f[(size_t)(LSEQ - 1) * NB * HID + off])
                             : __bfloat162float(g_hs_b[off]);
        float cv = (e < 512) ? g_c_enc[off] : g_c_enc[(size_t)NB * HID + off];
        hm = fmaxf(hm, hv);
        cm = fmaxf(cm, cv);
    }
    g_c_dec[idx] = cm;
    __nv_bfloat16 hb = __float2bfloat16(hm);
    g_hdec_bf[idx] = hb;
    g_feat[(size_t)b * 2048 + e] = hb;
    if (idx == 0) { g_barB_cnt = 0u; g_barB_gen = 0u; }
}

// ---------------- Phase C: all-timestep attention per (b,n), bf16 ctx out ----------------
#define ATTN_SMEM (64*1032*2 + 32*1024*2 + 32*72*4 + 32*64*2)
__global__ void __launch_bounds__(256) k_attn_all() {
    extern __shared__ char smc[];
    __nv_bfloat16* hsS = (__nv_bfloat16*)smc;
    __nv_bfloat16* qS  = (__nv_bfloat16*)(smc + 64 * 1032 * 2);
    float*         scS = (float*)(smc + 64 * 1032 * 2 + 32 * 1024 * 2);
    __nv_bfloat16* awS = (__nv_bfloat16*)(smc + 64 * 1032 * 2 + 32 * 1024 * 2 + 32 * 72 * 4);

    int nb = blockIdx.x;
    int b  = nb >> 2;
    int tid = threadIdx.x, lane = tid & 31, warp = tid >> 5;

    for (int c = tid; c < 64 * 128; c += 256) {
        int l = c >> 7, off = (c & 127) * 8;
        const __nv_bfloat16* src = (off < 512)
            ? g_hs_f + ((size_t)l * NB + nb) * HID + off
            : g_hs_b + ((size_t)l * NB + nb) * HID + (off - 512);
        *(uint4*)&hsS[l * 1032 + off] = *(const uint4*)src;
    }
    for (int c = tid; c < 32 * 512; c += 256) {
        int t = c >> 9, d2 = (c & 511) * 2;
        float2 f = *(const float2*)&g_q_all[((size_t)t * BATCH + b) * EH + d2];
        *(__nv_bfloat162*)&qS[t * 1024 + d2] = __float22bfloat162_rn(f);
    }
    __syncthreads();

    {
        int mi = warp >> 2, ni = warp & 3;
        wmma::fragment<wmma::accumulator, 16, 16, 16, float> acc;
        wmma::fill_fragment(acc, 0.f);
        for (int k = 0; k < 1024; k += 16) {
            wmma::fragment<wmma::matrix_a, 16, 16, 16, __nv_bfloat16, wmma::row_major> a;
            wmma::fragment<wmma::matrix_b, 16, 16, 16, __nv_bfloat16, wmma::col_major> bm;
            wmma::load_matrix_sync(a, qS + mi * 16 * 1024 + k, 1024);
            wmma::load_matrix_sync(bm, hsS + (ni * 16) * 1032 + k, 1032);
            wmma::mma_sync(acc, a, bm, acc);
        }
        wmma::store_matrix_sync(scS + mi * 16 * 72 + ni * 16, acc, 72, wmma::mem_row_major);
    }
    __syncthreads();

    for (int t = warp; t < 32; t += 8) {
        float s0 = scS[t * 72 + lane], s1 = scS[t * 72 + 32 + lane];
        float mx = fmaxf(s0, s1);
#pragma unroll
        for (int o = 16; o > 0; o >>= 1) mx = fmaxf(mx, __shfl_xor_sync(0xffffffffu, mx, o));
        float e0 = __expf(s0 - mx), e1 = __expf(s1 - mx);
        float sum = e0 + e1;
#pragma unroll
        for (int o = 16; o > 0; o >>= 1) sum += __shfl_xor_sync(0xffffffffu, sum, o);
        float inv = 1.f / sum;
        awS[t * 64 + lane]      = __float2bfloat16(e0 * inv);
        awS[t * 64 + 32 + lane] = __float2bfloat16(e1 * inv);
    }
    __syncthreads();

    {
        float* wsc = (float*)qS + warp * 1024;
        wmma::fragment<wmma::matrix_a, 16, 16, 16, __nv_bfloat16, wmma::row_major> a[2][4];
#pragma unroll
        for (int mi = 0; mi < 2; mi++)
#pragma unroll
            for (int kt = 0; kt < 4; kt++)
                wmma::load_matrix_sync(a[mi][kt], awS + mi * 16 * 64 + kt * 16, 64);
        for (int nt = 0; nt < 8; nt++) {
            int n0 = warp * 128 + nt * 16;
            wmma::fragment<wmma::accumulator, 16, 16, 16, float> acc[2];
            wmma::fill_fragment(acc[0], 0.f);
            wmma::fill_fragment(acc[1], 0.f);
#pragma unroll
            for (int kt = 0; kt < 4; kt++) {
                wmma::fragment<wmma::matrix_b, 16, 16, 16, __nv_bfloat16, wmma::row_major> bm;
                wmma::load_matrix_sync(bm, hsS + kt * 16 * 1032 + n0, 1032);
                wmma::mma_sync(acc[0], a[0][kt], bm, acc[0]);
                wmma::mma_sync(acc[1], a[1][kt], bm, acc[1]);
            }
            wmma::store_matrix_sync(wsc,       acc[0], 16, wmma::mem_row_major);
            wmma::store_matrix_sync(wsc + 256, acc[1], 16, wmma::mem_row_major);
            __syncwarp();
            {
                int tt = lane;
                const float* src = wsc + (tt >> 4) * 256 + (tt & 15) * 16;
                __nv_bfloat162 pk2[8];
#pragma unroll
                for (int h = 0; h < 8; h++)
                    pk2[h] = __float22bfloat162_rn(make_float2(src[h * 2], src[h * 2 + 1]));
                __nv_bfloat16* dst = g_ctx_bf + ((size_t)tt * NB + nb) * EH + n0;
                *(uint4*)dst       = *(uint4*)&pk2[0];
                *(uint4*)(dst + 8) = *(uint4*)&pk2[4];
            }
            __syncwarp();
        }
    }
}

// ---------------- Phase D ----------------
__global__ void k_ctxpool() {
    int idx = blockIdx.x * blockDim.x + threadIdx.x;
    int d  = idx & 1023;
    int tb = idx >> 10;
    int b  = tb & 255, t = tb >> 8;
    const __nv_bfloat16* base = g_ctx_bf + ((size_t)t * NB + b * 4) * EH + d;
    float m = fmaxf(
        fmaxf(__bfloat162float(base[0]), __bfloat162float(base[EH])),
        fmaxf(__bfloat162float(base[2 * EH]), __bfloat162float(base[3 * EH])));
    g_feat[(size_t)tb * 2048 + 1024 + d] = __float2bfloat16(m);
}

__global__ void k_out(float* __restrict__ out) {
    int b = threadIdx.x;
    float s = 0.f;
    for (int t = 0; t < TDEC; t++) s += g_nll[t * BATCH + b];
    out[b] = s;
}

// ---------------- host orchestration ----------------
extern "C" void kernel_launch(void* const* d_in, const int* in_sizes, int n_in,
                              void* d_out, int out_size) {
    const int*   exs     = (const int*)  d_in[0];
    const int*   cls     = (const int*)  d_in[1];
    const float* E       = (const float*)d_in[2];
    const float* Wi_f    = (const float*)d_in[3];
    const float* Wh_f    = (const float*)d_in[4];
    const float* b_f     = (const float*)d_in[5];
    const float* Wi_b    = (const float*)d_in[6];
    const float* Wh_b    = (const float*)d_in[7];
    const float* b_b     = (const float*)d_in[8];
    const float* W_attn  = (const float*)d_in[9];
    const float* W_comp  = (const float*)d_in[10];
    const float* b_comp  = (const float*)d_in[11];
    const float* v_Wi    = (const float*)d_in[12];
    const float* v_Wh    = (const float*)d_in[13];
    const float* v_b     = (const float*)d_in[14];
    const float* field   = (const float*)d_in[15];
    const int*   actions = (const int*)  d_in[16];
    float* out = (float*)d_out;

    cudaFuncSetAttribute(enc_persist, cudaFuncAttributeMaxDynamicSharedMemorySize, ENC_DYN);
    cudaFuncSetAttribute(k_attn_all, cudaFuncAttributeMaxDynamicSharedMemorySize, ATTN_SMEM);

    __nv_bfloat16 *p_field_bf, *p_vWi_bf, *p_feat, *p_Wattn_bf;
    float *p_vXWi, *p_q_all;
    cudaGetSymbolAddress((void**)&p_field_bf, g_field_bf);
    cudaGetSymbolAddress((void**)&p_vWi_bf, g_vWi_bf);
    cudaGetSymbolAddress((void**)&p_feat, g_feat);
    cudaGetSymbolAddress((void**)&p_Wattn_bf, g_Wattn_bf);
    cudaGetSymbolAddress((void**)&p_vXWi, g_vXWi);
    cudaGetSymbolAddress((void**)&p_q_all, g_q_all);

    // ---- setup ----
    k_embed<<<(LSEQ * NB * XDIM) / 256, 256>>>(exs, cls, E);
    k_wcat<<<(2 * KCAT * GATE) / 256, 256>>>(Wi_f, Wh_f, Wi_b, Wh_b);
    k_init<<<1, 32>>>();

    // ---- encoder (256 workers, 2/SM enforced) + conversions (20 helper blocks) ----
    enc_persist<<<276, 256, ENC_DYN>>>(b_f, b_b, W_attn, v_Wi, v_Wh, field, W_comp);

    // vXWi = field_emb @ v_Wi(interleaved)
    gemm_bf16<<<dim3(VG / BN, 1, 1), 256>>>(
        p_field_bf, p_vWi_bf, p_vXWi, TDEC, VG, EH, EH, VG, VG);

    // ---- decoder init ----
    k_pool<<<(BATCH * EH) / 256, 256>>>();

    // ---- Phase A: persistent v-LSTM recurrence (31 steps) ----
    vlstm_persist<<<128, 128>>>(v_b);

    // ---- Phase B: q_all = h_hist @ W_attn ----
    gemm_bf16<<<dim3(EH / BN, TB / BM), 256>>>(
        p_feat, p_Wattn_bf, p_q_all, TB, EH, EH, 2048, EH, EH);

    // ---- Phase C ----
    k_attn_all<<<NB, 256, ATTN_SMEM>>>();

    // ---- Phase D ----
    k_ctxpool<<<(TDEC * BATCH * EH) / 256, 256>>>();
    gemm_cls<<<dim3(1, TB / 64), 128>>>(b_comp, actions);
    k_out<<<1, BATCH>>>(out);
}